// round 5
// baseline (speedup 1.0000x reference)
#include <cstdint>
#include <cstddef>
#include <cuda_runtime.h>
#include <cuda_fp16.h>

// ---------------------------------------------------------------------------
// RegionAwareAttention  (B=8, Np=4096, Nr=32, C=768, H=12, D=64)
//   q  = patch @ Wq + bq                      (32768 x 768) fp16 GEMM
//   kv = region @ Wkv + bkv                   (  256 x 1536) fp16 GEMM
//   attn = softmax(scale * q.k * p2r + 1e-8)  scalar kernel, k/v in smem
//   x  = attn @ v                             fused in attention kernel
//   out = x @ Wp + bp                         (32768 x 768) fp16 GEMM -> fp32
// ---------------------------------------------------------------------------

#define BATCH 8
#define NP    4096
#define NR    32
#define CDIM  768
#define NHEAD 12
#define HDIM  64
#define MROWS (BATCH * NP)        // 32768
#define RROWS (BATCH * NR)        // 256

typedef unsigned int u32;

// ---------------- scratch (static device globals; no runtime alloc) --------
__device__ __half g_A16 [MROWS * CDIM];     // patch fp16
__device__ __half g_Wq16[CDIM * CDIM];
__device__ __half g_Wkv16[CDIM * 2 * CDIM];
__device__ __half g_Wp16[CDIM * CDIM];
__device__ __half g_R16 [RROWS * CDIM];     // region fp16
__device__ __half g_q16 [MROWS * CDIM];     // q output fp16
__device__ __half g_kv16[RROWS * 2 * CDIM]; // kv output fp16
__device__ __half g_x16 [MROWS * CDIM];     // attention output fp16

// ---------------- fp32 -> fp16 convert -------------------------------------
__global__ void cvt_f32_f16(const float* __restrict__ in, __half* __restrict__ out, int n4)
{
    int i = blockIdx.x * blockDim.x + threadIdx.x;
    if (i < n4) {
        float4 v = reinterpret_cast<const float4*>(in)[i];
        __half2* o = reinterpret_cast<__half2*>(out) + 2 * i;
        o[0] = __floats2half2_rn(v.x, v.y);
        o[1] = __floats2half2_rn(v.z, v.w);
    }
}

// ---------------- mma helpers ----------------------------------------------
__device__ __forceinline__ void ldsm_x4(u32* r, const void* p)
{
    u32 a = (u32)__cvta_generic_to_shared(p);
    asm volatile("ldmatrix.sync.aligned.m8n8.x4.shared.b16 {%0,%1,%2,%3}, [%4];\n"
                 : "=r"(r[0]), "=r"(r[1]), "=r"(r[2]), "=r"(r[3]) : "r"(a));
}
__device__ __forceinline__ void ldsm_x2t(u32* r, const void* p)
{
    u32 a = (u32)__cvta_generic_to_shared(p);
    asm volatile("ldmatrix.sync.aligned.m8n8.x2.trans.shared.b16 {%0,%1}, [%2];\n"
                 : "=r"(r[0]), "=r"(r[1]) : "r"(a));
}
__device__ __forceinline__ void mma_16816(float* c, const u32* a, const u32* b)
{
    asm volatile("mma.sync.aligned.m16n8k16.row.col.f32.f16.f16.f32 "
                 "{%0,%1,%2,%3}, {%4,%5,%6,%7}, {%8,%9}, {%0,%1,%2,%3};\n"
                 : "+f"(c[0]), "+f"(c[1]), "+f"(c[2]), "+f"(c[3])
                 : "r"(a[0]), "r"(a[1]), "r"(a[2]), "r"(a[3]), "r"(b[0]), "r"(b[1]));
}

__device__ __forceinline__ void store2(__half* p, float x, float y)
{
    *reinterpret_cast<__half2*>(p) = __floats2half2_rn(x, y);
}
__device__ __forceinline__ void store2(float* p, float x, float y)
{
    float2 v; v.x = x; v.y = y;
    *reinterpret_cast<float2*>(p) = v;
}

// ---------------- fp16 GEMM:  C[M,N] = A[M,K] @ W[K,N] + bias --------------
// BM=128 BN=128 BK=32, 256 threads (8 warps as 4m x 2n, warp tile 32x64)
template <typename OutT>
__global__ void __launch_bounds__(256)
hgemm(const __half* __restrict__ A, const __half* __restrict__ W,
      const float* __restrict__ bias, OutT* __restrict__ C,
      int M, int N, int K)
{
    const int BM = 128, BN = 128, BK = 32;
    __shared__ __half As[128][BK + 8];
    __shared__ __half Bs[BK][BN + 8];
    (void)BM;

    const int tid  = threadIdx.x;
    const int warp = tid >> 5;
    const int lane = tid & 31;
    const int bm = blockIdx.y * 128;
    const int bn = blockIdx.x * 128;
    const int wm = (warp & 3) * 32;   // warp row offset
    const int wn = (warp >> 2) * 64;  // warp col offset

    float acc[2][8][4];
#pragma unroll
    for (int mi = 0; mi < 2; mi++)
#pragma unroll
        for (int ni = 0; ni < 8; ni++)
#pragma unroll
            for (int j = 0; j < 4; j++) acc[mi][ni][j] = 0.f;

    // global->smem load mapping (uint4 = 8 halves)
    int a_row[2], a_col[2], b_row[2], b_col[2];
#pragma unroll
    for (int i = 0; i < 2; i++) {
        int idx = tid + i * 256;
        a_row[i] = idx >> 2;  a_col[i] = (idx & 3) * 8;   // 128 rows x 4 chunks
        b_row[i] = idx >> 4;  b_col[i] = (idx & 15) * 8;  // 32 rows x 16 chunks
    }

    uint4 pa[2], pb[2];
#pragma unroll
    for (int i = 0; i < 2; i++) {
        pa[i] = *reinterpret_cast<const uint4*>(A + (bm + a_row[i]) * K + a_col[i]);
        pb[i] = *reinterpret_cast<const uint4*>(W + b_row[i] * N + bn + b_col[i]);
    }

    const int nk = K / BK;
    for (int kt = 0; kt < nk; kt++) {
#pragma unroll
        for (int i = 0; i < 2; i++) {
            *reinterpret_cast<uint4*>(&As[a_row[i]][a_col[i]]) = pa[i];
            *reinterpret_cast<uint4*>(&Bs[b_row[i]][b_col[i]]) = pb[i];
        }
        __syncthreads();

        if (kt + 1 < nk) {
            int k0 = (kt + 1) * BK;
#pragma unroll
            for (int i = 0; i < 2; i++) {
                pa[i] = *reinterpret_cast<const uint4*>(A + (bm + a_row[i]) * K + k0 + a_col[i]);
                pb[i] = *reinterpret_cast<const uint4*>(W + (k0 + b_row[i]) * N + bn + b_col[i]);
            }
        }

#pragma unroll
        for (int kk = 0; kk < 2; kk++) {
            u32 af[2][4], bf[8][2];
#pragma unroll
            for (int mi = 0; mi < 2; mi++)
                ldsm_x4(af[mi], &As[wm + mi * 16 + (lane & 15)][kk * 16 + (lane >> 4) * 8]);
#pragma unroll
            for (int ni = 0; ni < 8; ni++)
                ldsm_x2t(bf[ni], &Bs[kk * 16 + (lane & 15)][wn + ni * 8]);
#pragma unroll
            for (int mi = 0; mi < 2; mi++)
#pragma unroll
                for (int ni = 0; ni < 8; ni++)
                    mma_16816(acc[mi][ni], af[mi], bf[ni]);
        }
        __syncthreads();
    }

    // epilogue
    const int g  = lane >> 2;
    const int t2 = (lane & 3) * 2;
#pragma unroll
    for (int mi = 0; mi < 2; mi++) {
#pragma unroll
        for (int ni = 0; ni < 8; ni++) {
            int row = bm + wm + mi * 16 + g;
            int col = bn + wn + ni * 8 + t2;
            float b0 = bias[col], b1 = bias[col + 1];
            store2(C + row * N + col,       acc[mi][ni][0] + b0, acc[mi][ni][1] + b1);
            store2(C + (row + 8) * N + col, acc[mi][ni][2] + b0, acc[mi][ni][3] + b1);
        }
    }
}

// ---------------- attention ------------------------------------------------
// grid (Np/256, H, B), block 256. Warp = 32 consecutive p, fixed (b,h).
// k/v staged in smem (fp32). Lane-uniform smem reads -> broadcast.
__global__ void __launch_bounds__(256)
attn_kernel(const __half* __restrict__ Q, const __half* __restrict__ KV,
            const float* __restrict__ P2R, __half* __restrict__ X)
{
    const int b  = blockIdx.z;
    const int h  = blockIdx.y;
    const int p0 = blockIdx.x * 256;
    const int tid = threadIdx.x, warp = tid >> 5, lane = tid & 31;

    __shared__ float  ks[NR * HDIM];
    __shared__ float  vs[NR * HDIM];
    __shared__ __half ob[8][32][34];   // padded: stride 34 halves, conflict-free

    // stage k,v for this (b,h): 2048 halves each, 8 per thread
    {
        int r = tid >> 3;
        int c = (tid & 7) * 8;
        const __half* kb = KV + (b * NR + r) * (2 * CDIM) + h * HDIM + c;
        uint4 kraw = *reinterpret_cast<const uint4*>(kb);
        uint4 vraw = *reinterpret_cast<const uint4*>(kb + CDIM);
        const __half2* kh = reinterpret_cast<const __half2*>(&kraw);
        const __half2* vh = reinterpret_cast<const __half2*>(&vraw);
#pragma unroll
        for (int j = 0; j < 4; j++) {
            float2 fk = __half22float2(kh[j]);
            float2 fv = __half22float2(vh[j]);
            ks[r * HDIM + c + 2 * j]     = fk.x;
            ks[r * HDIM + c + 2 * j + 1] = fk.y;
            vs[r * HDIM + c + 2 * j]     = fv.x;
            vs[r * HDIM + c + 2 * j + 1] = fv.y;
        }
    }
    __syncthreads();

    const int p   = p0 + warp * 32 + lane;
    const int row = b * NP + p;

    // load q row -> fp32 regs
    float qf[HDIM];
    {
        const uint4* q4 = reinterpret_cast<const uint4*>(Q + row * CDIM + h * HDIM);
#pragma unroll
        for (int i = 0; i < 8; i++) {
            uint4 raw = q4[i];
            const __half2* hh = reinterpret_cast<const __half2*>(&raw);
#pragma unroll
            for (int j = 0; j < 4; j++) {
                float2 f = __half22float2(hh[j]);
                qf[i * 8 + 2 * j]     = f.x;
                qf[i * 8 + 2 * j + 1] = f.y;
            }
        }
    }

    // scores
    float s[NR];
    const float4* k4base = reinterpret_cast<const float4*>(ks);
#pragma unroll
    for (int r = 0; r < NR; r++) {
        float a0 = 0.f, a1 = 0.f, a2 = 0.f, a3 = 0.f;
#pragma unroll
        for (int j = 0; j < 16; j++) {
            float4 kv4 = k4base[r * 16 + j];
            a0 += qf[4 * j + 0] * kv4.x;
            a1 += qf[4 * j + 1] * kv4.y;
            a2 += qf[4 * j + 2] * kv4.z;
            a3 += qf[4 * j + 3] * kv4.w;
        }
        s[r] = (a0 + a1) + (a2 + a3);
    }

    // scale * p2r + eps
    const float4* pr4 = reinterpret_cast<const float4*>(P2R + row * NR);
#pragma unroll
    for (int j = 0; j < 8; j++) {
        float4 w = pr4[j];
        s[4 * j + 0] = s[4 * j + 0] * (0.125f * w.x) + 1e-8f;
        s[4 * j + 1] = s[4 * j + 1] * (0.125f * w.y) + 1e-8f;
        s[4 * j + 2] = s[4 * j + 2] * (0.125f * w.z) + 1e-8f;
        s[4 * j + 3] = s[4 * j + 3] * (0.125f * w.w) + 1e-8f;
    }

    // softmax over 32 regions (per-thread, fp32)
    float m = s[0];
#pragma unroll
    for (int r = 1; r < NR; r++) m = fmaxf(m, s[r]);
    float sum = 0.f;
#pragma unroll
    for (int r = 0; r < NR; r++) { s[r] = __expf(s[r] - m); sum += s[r]; }
    float inv = 1.0f / sum;
#pragma unroll
    for (int r = 0; r < NR; r++) s[r] *= inv;

    // output = attn @ v ; two 32-wide halves to keep smem outbuf small
    const float4* v4base = reinterpret_cast<const float4*>(vs);
#pragma unroll
    for (int hf = 0; hf < 2; hf++) {
#pragma unroll
        for (int d4 = 0; d4 < 8; d4++) {
            float x0 = 0.f, x1 = 0.f, x2 = 0.f, x3 = 0.f;
#pragma unroll
            for (int r = 0; r < NR; r++) {
                float4 vv = v4base[r * 16 + hf * 8 + d4];
                x0 += s[r] * vv.x;
                x1 += s[r] * vv.y;
                x2 += s[r] * vv.z;
                x3 += s[r] * vv.w;
            }
            __half2* dst = reinterpret_cast<__half2*>(&ob[warp][lane][d4 * 4]);
            dst[0] = __floats2half2_rn(x0, x1);
            dst[1] = __floats2half2_rn(x2, x3);
        }
        __syncwarp();
        // coalesced copy-out: 32 rows x 32 halves
#pragma unroll
        for (int i = 0; i < 16; i++) {
            int idx = lane + i * 32;
            int rr  = idx >> 4;
            int c2  = idx & 15;
            __half2 val = *reinterpret_cast<__half2*>(&ob[warp][rr][c2 * 2]);
            __half* dst = X + (b * NP + p0 + warp * 32 + rr) * CDIM
                            + h * HDIM + hf * 32 + c2 * 2;
            *reinterpret_cast<__half2*>(dst) = val;
        }
        __syncwarp();
    }
}

// ---------------- launcher -------------------------------------------------
extern "C" void kernel_launch(void* const* d_in, const int* in_sizes, int n_in,
                              void* d_out, int out_size)
{
    const float* patch  = (const float*)d_in[0];
    const float* region = (const float*)d_in[1];
    const float* p2r    = (const float*)d_in[2];
    const float* Wq     = (const float*)d_in[3];
    const float* bq     = (const float*)d_in[4];
    const float* Wkv    = (const float*)d_in[5];
    const float* bkv    = (const float*)d_in[6];
    const float* Wp     = (const float*)d_in[7];
    const float* bp     = (const float*)d_in[8];
    float* out = (float*)d_out;

    __half *A16, *Wq16, *Wkv16, *Wp16, *R16, *q16, *kv16, *x16;
    cudaGetSymbolAddress((void**)&A16,  g_A16);
    cudaGetSymbolAddress((void**)&Wq16, g_Wq16);
    cudaGetSymbolAddress((void**)&Wkv16,g_Wkv16);
    cudaGetSymbolAddress((void**)&Wp16, g_Wp16);
    cudaGetSymbolAddress((void**)&R16,  g_R16);
    cudaGetSymbolAddress((void**)&q16,  g_q16);
    cudaGetSymbolAddress((void**)&kv16, g_kv16);
    cudaGetSymbolAddress((void**)&x16,  g_x16);

    // fp32 -> fp16 converts
    {
        int n4;
        n4 = (MROWS * CDIM) / 4;      cvt_f32_f16<<<(n4 + 255) / 256, 256>>>(patch,  A16,  n4);
        n4 = (CDIM * CDIM) / 4;       cvt_f32_f16<<<(n4 + 255) / 256, 256>>>(Wq,     Wq16, n4);
        n4 = (CDIM * 2 * CDIM) / 4;   cvt_f32_f16<<<(n4 + 255) / 256, 256>>>(Wkv,    Wkv16,n4);
        n4 = (CDIM * CDIM) / 4;       cvt_f32_f16<<<(n4 + 255) / 256, 256>>>(Wp,     Wp16, n4);
        n4 = (RROWS * CDIM) / 4;      cvt_f32_f16<<<(n4 + 255) / 256, 256>>>(region, R16,  n4);
    }

    // q = patch @ Wq + bq
    hgemm<__half><<<dim3(CDIM / 128, MROWS / 128), 256>>>(A16, Wq16, bq, q16,
                                                          MROWS, CDIM, CDIM);
    // kv = region @ Wkv + bkv
    hgemm<__half><<<dim3(2 * CDIM / 128, RROWS / 128), 256>>>(R16, Wkv16, bkv, kv16,
                                                              RROWS, 2 * CDIM, CDIM);
    // attention -> x16
    attn_kernel<<<dim3(NP / 256, NHEAD, BATCH), 256>>>(q16, kv16, p2r, x16);

    // out = x @ Wp + bp   (fp32 output)
    hgemm<float><<<dim3(CDIM / 128, MROWS / 128), 256>>>(x16, Wp16, bp, out,
                                                         MROWS, CDIM, CDIM);
}

// round 7
// speedup vs baseline: 1.5091x; 1.5091x over previous
#include <cstdint>
#include <cstddef>
#include <cuda_runtime.h>
#include <cuda_fp16.h>

// ---------------------------------------------------------------------------
// RegionAwareAttention  (B=8, Np=4096, Nr=32, C=768, H=12, D=64)
// Restructured: fold Wq into K and Wp into V (Nr, D small):
//   kv   = region @ Wkv + bkv                       (tiny GEMM)
//   QKT[b][c][hr] = sum_d Wq[c,hD+d] * k[b,r,h,d]   (tiny)
//   VP [b][hr][c] = sum_d v[b,r,h,d] * Wp[hD+d,c]   (tiny)
//   qb [b][hr]    = sum_d bq[hD+d]   * k[b,r,h,d]   (tiny)
//   S    = patch @ QKT[b] + qb    batched GEMM  M=4096 K=768 N=384  (19.3 GF)
//   attn = softmax(S*scale*p2r + 1e-8)   elementwise
//   out  = attn @ VP[b] + bp      batched GEMM  M=4096 K=384 N=768  (19.3 GF)
// ---------------------------------------------------------------------------

#define BATCH 8
#define NP    4096
#define NR    32
#define CDIM  768
#define NHEAD 12
#define HDIM  64
#define HR    (NHEAD * NR)        // 384
#define MROWS (BATCH * NP)        // 32768
#define RROWS (BATCH * NR)        // 256

typedef unsigned int u32;

// ---------------- scratch (static device globals; no runtime alloc) --------
__device__ __half g_A16  [MROWS * CDIM];       // patch fp16
__device__ __half g_WqT16[CDIM * CDIM];        // Wq transposed fp16
__device__ __half g_Wkv16[CDIM * 2 * CDIM];
__device__ __half g_Wp16 [CDIM * CDIM];
__device__ __half g_R16  [RROWS * CDIM];       // region fp16
__device__ __half g_kv16 [RROWS * 2 * CDIM];   // kv output fp16
__device__ __half g_QKT  [BATCH * CDIM * HR];  // (768 x 384) per batch
__device__ __half g_VP   [BATCH * HR * CDIM];  // (384 x 768) per batch
__device__ float  g_qb   [BATCH * HR];
__device__ float  g_S    [MROWS * HR];         // raw scores fp32
__device__ __half g_attn [MROWS * HR];         // softmaxed fp16

// ---------------- fp32 -> fp16 convert -------------------------------------
__global__ void cvt_f32_f16(const float* __restrict__ in, __half* __restrict__ out, int n4)
{
    int i = blockIdx.x * blockDim.x + threadIdx.x;
    if (i < n4) {
        float4 v = reinterpret_cast<const float4*>(in)[i];
        __half2* o = reinterpret_cast<__half2*>(out) + 2 * i;
        o[0] = __floats2half2_rn(v.x, v.y);
        o[1] = __floats2half2_rn(v.z, v.w);
    }
}

// ---------------- fp32 -> fp16 transpose (768x768) -------------------------
__global__ void transpose_cvt(const float* __restrict__ in, __half* __restrict__ out)
{
    __shared__ float t[32][33];
    int bx = blockIdx.x * 32, by = blockIdx.y * 32;
    int tx = threadIdx.x, ty = threadIdx.y;   // (32, 8)
#pragma unroll
    for (int i = 0; i < 32; i += 8)
        t[ty + i][tx] = in[(by + ty + i) * CDIM + bx + tx];
    __syncthreads();
#pragma unroll
    for (int i = 0; i < 32; i += 8)
        out[(bx + ty + i) * CDIM + by + tx] = __float2half(t[tx][ty + i]);
}

// ---------------- mma helpers ----------------------------------------------
__device__ __forceinline__ void ldsm_x4(u32* r, const void* p)
{
    u32 a = (u32)__cvta_generic_to_shared(p);
    asm volatile("ldmatrix.sync.aligned.m8n8.x4.shared.b16 {%0,%1,%2,%3}, [%4];\n"
                 : "=r"(r[0]), "=r"(r[1]), "=r"(r[2]), "=r"(r[3]) : "r"(a));
}
__device__ __forceinline__ void ldsm_x2t(u32* r, const void* p)
{
    u32 a = (u32)__cvta_generic_to_shared(p);
    asm volatile("ldmatrix.sync.aligned.m8n8.x2.trans.shared.b16 {%0,%1}, [%2];\n"
                 : "=r"(r[0]), "=r"(r[1]) : "r"(a));
}
__device__ __forceinline__ void mma_16816(float* c, const u32* a, const u32* b)
{
    asm volatile("mma.sync.aligned.m16n8k16.row.col.f32.f16.f16.f32 "
                 "{%0,%1,%2,%3}, {%4,%5,%6,%7}, {%8,%9}, {%0,%1,%2,%3};\n"
                 : "+f"(c[0]), "+f"(c[1]), "+f"(c[2]), "+f"(c[3])
                 : "r"(a[0]), "r"(a[1]), "r"(a[2]), "r"(a[3]), "r"(b[0]), "r"(b[1]));
}

__device__ __forceinline__ void store2(__half* p, float x, float y)
{
    *reinterpret_cast<__half2*>(p) = __floats2half2_rn(x, y);
}
__device__ __forceinline__ void store2(float* p, float x, float y)
{
    float2 v; v.x = x; v.y = y;
    *reinterpret_cast<float2*>(p) = v;
}

// ---------------- batched fp16 GEMM: C[b] = A[b] @ W[b] + bias[b] ----------
// BM=128 BN=128 BK=32, 256 threads (8 warps as 4m x 2n, warp tile 32x64)
template <typename OutT>
__global__ void __launch_bounds__(256)
hgemm(const __half* __restrict__ A0, const __half* __restrict__ W0,
      const float* __restrict__ bias0, OutT* __restrict__ C0,
      int M, int N, int K, int sA, int sW, int sBias, int sC)
{
    const int BK = 32;
    __shared__ __half As[128][BK + 8];
    __shared__ __half Bs[BK][128 + 8];

    const int bz = blockIdx.z;
    const __half* A = A0 + (long)bz * sA;
    const __half* W = W0 + (long)bz * sW;
    const float* bias = bias0 + (long)bz * sBias;
    OutT* C = C0 + (long)bz * sC;

    const int tid  = threadIdx.x;
    const int warp = tid >> 5;
    const int lane = tid & 31;
    const int bm = blockIdx.y * 128;
    const int bn = blockIdx.x * 128;
    const int wm = (warp & 3) * 32;   // warp row offset
    const int wn = (warp >> 2) * 64;  // warp col offset

    float acc[2][8][4];
#pragma unroll
    for (int mi = 0; mi < 2; mi++)
#pragma unroll
        for (int ni = 0; ni < 8; ni++)
#pragma unroll
            for (int j = 0; j < 4; j++) acc[mi][ni][j] = 0.f;

    int a_row[2], a_col[2], b_row[2], b_col[2];
#pragma unroll
    for (int i = 0; i < 2; i++) {
        int idx = tid + i * 256;
        a_row[i] = idx >> 2;  a_col[i] = (idx & 3) * 8;   // 128 rows x 4 chunks
        b_row[i] = idx >> 4;  b_col[i] = (idx & 15) * 8;  // 32 rows x 16 chunks
    }

    uint4 pa[2], pb[2];
#pragma unroll
    for (int i = 0; i < 2; i++) {
        pa[i] = *reinterpret_cast<const uint4*>(A + (bm + a_row[i]) * K + a_col[i]);
        pb[i] = *reinterpret_cast<const uint4*>(W + b_row[i] * N + bn + b_col[i]);
    }

    const int nk = K / BK;
    for (int kt = 0; kt < nk; kt++) {
#pragma unroll
        for (int i = 0; i < 2; i++) {
            *reinterpret_cast<uint4*>(&As[a_row[i]][a_col[i]]) = pa[i];
            *reinterpret_cast<uint4*>(&Bs[b_row[i]][b_col[i]]) = pb[i];
        }
        __syncthreads();

        if (kt + 1 < nk) {
            int k0 = (kt + 1) * BK;
#pragma unroll
            for (int i = 0; i < 2; i++) {
                pa[i] = *reinterpret_cast<const uint4*>(A + (bm + a_row[i]) * K + k0 + a_col[i]);
                pb[i] = *reinterpret_cast<const uint4*>(W + (k0 + b_row[i]) * N + bn + b_col[i]);
            }
        }

#pragma unroll
        for (int kk = 0; kk < 2; kk++) {
            u32 af[2][4], bf[8][2];
#pragma unroll
            for (int mi = 0; mi < 2; mi++)
                ldsm_x4(af[mi], &As[wm + mi * 16 + (lane & 15)][kk * 16 + (lane >> 4) * 8]);
#pragma unroll
            for (int ni = 0; ni < 8; ni++)
                ldsm_x2t(bf[ni], &Bs[kk * 16 + (lane & 15)][wn + ni * 8]);
#pragma unroll
            for (int mi = 0; mi < 2; mi++)
#pragma unroll
                for (int ni = 0; ni < 8; ni++)
                    mma_16816(acc[mi][ni], af[mi], bf[ni]);
        }
        __syncthreads();
    }

    const int g  = lane >> 2;
    const int t2 = (lane & 3) * 2;
#pragma unroll
    for (int mi = 0; mi < 2; mi++) {
#pragma unroll
        for (int ni = 0; ni < 8; ni++) {
            int row = bm + wm + mi * 16 + g;
            int col = bn + wn + ni * 8 + t2;
            float b0 = bias[col], b1 = bias[col + 1];
            store2(C + row * N + col,       acc[mi][ni][0] + b0, acc[mi][ni][1] + b1);
            store2(C + (row + 8) * N + col, acc[mi][ni][2] + b0, acc[mi][ni][3] + b1);
        }
    }
}

// ---------------- kv -> QKT, VP projections --------------------------------
// grid (B*H, CDIM/128), block 128. Thread = one output column c.
__global__ void __launch_bounds__(128)
project_kv(const __half* __restrict__ kv, const __half* __restrict__ WqT,
           const __half* __restrict__ Wp, __half* __restrict__ QKT,
           __half* __restrict__ VP)
{
    const int bh = blockIdx.x;
    const int b = bh / NHEAD, h = bh % NHEAD;
    const int c = blockIdx.y * 128 + threadIdx.x;

    __shared__ float ksm[NR][HDIM];
    __shared__ float vsm[NR][HDIM];

    // load k,v tiles for (b,h): 2048 halves each
    for (int i = threadIdx.x; i < NR * HDIM / 8; i += 128) {
        int r = (i * 8) / HDIM;
        int d = (i * 8) % HDIM;
        const __half* src = kv + (b * NR + r) * (2 * CDIM) + h * HDIM + d;
        uint4 kraw = *reinterpret_cast<const uint4*>(src);
        uint4 vraw = *reinterpret_cast<const uint4*>(src + CDIM);
        const __half2* kh = reinterpret_cast<const __half2*>(&kraw);
        const __half2* vh = reinterpret_cast<const __half2*>(&vraw);
#pragma unroll
        for (int j = 0; j < 4; j++) {
            float2 fk = __half22float2(kh[j]);
            float2 fv = __half22float2(vh[j]);
            ksm[r][d + 2 * j]     = fk.x;
            ksm[r][d + 2 * j + 1] = fk.y;
            vsm[r][d + 2 * j]     = fv.x;
            vsm[r][d + 2 * j + 1] = fv.y;
        }
    }
    __syncthreads();

    float acc[NR];

    // QKT[b][c][h*32+r] = sum_d WqT[hD+d, c] * k[r][d]
#pragma unroll
    for (int r = 0; r < NR; r++) acc[r] = 0.f;
    for (int d = 0; d < HDIM; d++) {
        float w = __half2float(WqT[(h * HDIM + d) * CDIM + c]);
#pragma unroll
        for (int r = 0; r < NR; r++) acc[r] += ksm[r][d] * w;
    }
    {
        __half* dst = QKT + (long)b * CDIM * HR + c * HR + h * NR;
#pragma unroll
        for (int r = 0; r < NR; r++) dst[r] = __float2half(acc[r]);
    }

    // VP[b][h*32+r][c] = sum_d v[r][d] * Wp[hD+d, c]
#pragma unroll
    for (int r = 0; r < NR; r++) acc[r] = 0.f;
    for (int d = 0; d < HDIM; d++) {
        float w = __half2float(Wp[(h * HDIM + d) * CDIM + c]);
#pragma unroll
        for (int r = 0; r < NR; r++) acc[r] += vsm[r][d] * w;
    }
    {
        __half* dst = VP + (long)b * HR * CDIM + h * NR * CDIM + c;
#pragma unroll
        for (int r = 0; r < NR; r++) dst[r * CDIM] = __float2half(acc[r]);
    }
}

// ---------------- qb[b][hr] = bq_h . k[b,r,h,:] ----------------------------
__global__ void qb_kernel(const __half* __restrict__ kv, const float* __restrict__ bq,
                          float* __restrict__ qb)
{
    int b = blockIdx.x;
    int hr = threadIdx.x;             // 384
    int h = hr / NR, r = hr % NR;
    const __half* kk = kv + (b * NR + r) * (2 * CDIM) + h * HDIM;
    float a = 0.f;
#pragma unroll
    for (int d = 0; d < HDIM; d++) a += bq[h * HDIM + d] * __half2float(kk[d]);
    qb[b * HR + hr] = a;
}

// ---------------- softmax: attn = softmax(S*scale*p2r + 1e-8) --------------
// thread = one (row, h); reads 32 fp32 scores + 32 p2r, writes 32 fp16
__global__ void __launch_bounds__(256)
softmax_kernel(const float* __restrict__ S, const float* __restrict__ P2R,
               __half* __restrict__ attn)
{
    int gidx = blockIdx.x * 256 + threadIdx.x;    // over MROWS*NHEAD
    int row = gidx / NHEAD;
    int h = gidx % NHEAD;

    const float4* sp = reinterpret_cast<const float4*>(S + (long)row * HR + h * NR);
    const float4* wp = reinterpret_cast<const float4*>(P2R + (long)row * NR);

    float s[NR];
#pragma unroll
    for (int j = 0; j < NR / 4; j++) {
        float4 sv = sp[j];
        float4 w  = wp[j];
        s[4 * j + 0] = sv.x * (0.125f * w.x) + 1e-8f;
        s[4 * j + 1] = sv.y * (0.125f * w.y) + 1e-8f;
        s[4 * j + 2] = sv.z * (0.125f * w.z) + 1e-8f;
        s[4 * j + 3] = sv.w * (0.125f * w.w) + 1e-8f;
    }

    float m = s[0];
#pragma unroll
    for (int r = 1; r < NR; r++) m = fmaxf(m, s[r]);
    float sum = 0.f;
#pragma unroll
    for (int r = 0; r < NR; r++) { s[r] = __expf(s[r] - m); sum += s[r]; }
    float inv = 1.0f / sum;

    __half2 packed[NR / 2];
#pragma unroll
    for (int j = 0; j < NR / 2; j++)
        packed[j] = __floats2half2_rn(s[2 * j] * inv, s[2 * j + 1] * inv);

    uint4* dst = reinterpret_cast<uint4*>(attn + (long)row * HR + h * NR);
    const uint4* src = reinterpret_cast<const uint4*>(packed);
#pragma unroll
    for (int j = 0; j < 4; j++) dst[j] = src[j];
}

// ---------------- launcher -------------------------------------------------
extern "C" void kernel_launch(void* const* d_in, const int* in_sizes, int n_in,
                              void* d_out, int out_size)
{
    const float* patch  = (const float*)d_in[0];
    const float* region = (const float*)d_in[1];
    const float* p2r    = (const float*)d_in[2];
    const float* Wq     = (const float*)d_in[3];
    const float* bq     = (const float*)d_in[4];
    const float* Wkv    = (const float*)d_in[5];
    const float* bkv    = (const float*)d_in[6];
    const float* Wp     = (const float*)d_in[7];
    const float* bp     = (const float*)d_in[8];
    float* out = (float*)d_out;

    __half *A16, *WqT16, *Wkv16, *Wp16, *R16, *kv16, *QKT, *VP, *attn;
    float *qb, *S;
    cudaGetSymbolAddress((void**)&A16,   g_A16);
    cudaGetSymbolAddress((void**)&WqT16, g_WqT16);
    cudaGetSymbolAddress((void**)&Wkv16, g_Wkv16);
    cudaGetSymbolAddress((void**)&Wp16,  g_Wp16);
    cudaGetSymbolAddress((void**)&R16,   g_R16);
    cudaGetSymbolAddress((void**)&kv16,  g_kv16);
    cudaGetSymbolAddress((void**)&QKT,   g_QKT);
    cudaGetSymbolAddress((void**)&VP,    g_VP);
    cudaGetSymbolAddress((void**)&attn,  g_attn);
    cudaGetSymbolAddress((void**)&qb,    g_qb);
    cudaGetSymbolAddress((void**)&S,     g_S);

    // fp32 -> fp16 converts (+ Wq transpose)
    {
        int n4;
        n4 = (MROWS * CDIM) / 4;      cvt_f32_f16<<<(n4 + 255) / 256, 256>>>(patch,  A16,   n4);
        n4 = (CDIM * 2 * CDIM) / 4;   cvt_f32_f16<<<(n4 + 255) / 256, 256>>>(Wkv,    Wkv16, n4);
        n4 = (CDIM * CDIM) / 4;       cvt_f32_f16<<<(n4 + 255) / 256, 256>>>(Wp,     Wp16,  n4);
        n4 = (RROWS * CDIM) / 4;      cvt_f32_f16<<<(n4 + 255) / 256, 256>>>(region, R16,   n4);
        transpose_cvt<<<dim3(CDIM / 32, CDIM / 32), dim3(32, 8)>>>(Wq, WqT16);
    }

    // kv = region @ Wkv + bkv   (256 x 1536)
    hgemm<__half><<<dim3(2 * CDIM / 128, RROWS / 128, 1), 256>>>(
        R16, Wkv16, bkv, kv16, RROWS, 2 * CDIM, CDIM, 0, 0, 0, 0);

    // QKT / VP projections + qb
    project_kv<<<dim3(BATCH * NHEAD, CDIM / 128), 128>>>(kv16, WqT16, Wp16, QKT, VP);
    qb_kernel<<<BATCH, HR>>>(kv16, bq, qb);

    // S = patch @ QKT[b] + qb[b]   batched: M=4096 N=384 K=768
    hgemm<float><<<dim3(HR / 128, NP / 128, BATCH), 256>>>(
        A16, QKT, qb, S, NP, HR, CDIM,
        NP * CDIM, CDIM * HR, HR, NP * HR);

    // attn = softmax(S * scale * p2r + 1e-8)
    softmax_kernel<<<(MROWS * NHEAD) / 256, 256>>>(S, p2r, attn);

    // out = attn @ VP[b] + bp   batched: M=4096 N=768 K=384
    hgemm<float><<<dim3(CDIM / 128, NP / 128, BATCH), 256>>>(
        attn, VP, bp, out, NP, CDIM, HR,
        NP * HR, HR * CDIM, 0, NP * CDIM);
}

// round 8
// speedup vs baseline: 1.5180x; 1.0059x over previous
#include <cstdint>
#include <cstddef>
#include <cuda_runtime.h>
#include <cuda_fp16.h>

// ---------------------------------------------------------------------------
// RegionAwareAttention  (B=8, Np=4096, Nr=32, C=768, H=12, D=64)
// Restructured: fold Wq into K and Wp into V (Nr, D small):
//   kv   = region @ Wkv + bkv                       (tiny GEMM)
//   QKT[b][c][hr] = sum_d Wq[c,hD+d] * k[b,r,h,d]   (tiny)
//   VP [b][hr][c] = sum_d v[b,r,h,d] * Wp[hD+d,c]   (tiny)
//   qb [b][hr]    = sum_d bq[hD+d]   * k[b,r,h,d]   (tiny)
//   S    = patch @ QKT[b] + qb    batched GEMM  M=4096 K=768 N=384  (19.3 GF)
//   attn = softmax(S*scale*p2r + 1e-8)   elementwise
//   out  = attn @ VP[b] + bp      batched GEMM  M=4096 K=384 N=768  (19.3 GF)
// ---------------------------------------------------------------------------

#define BATCH 8
#define NP    4096
#define NR    32
#define CDIM  768
#define NHEAD 12
#define HDIM  64
#define HR    (NHEAD * NR)        // 384
#define MROWS (BATCH * NP)        // 32768
#define RROWS (BATCH * NR)        // 256

typedef unsigned int u32;

// ---------------- scratch (static device globals; no runtime alloc) --------
__device__ __half g_A16  [MROWS * CDIM];       // patch fp16
__device__ __half g_WqT16[CDIM * CDIM];        // Wq transposed fp16
__device__ __half g_Wkv16[CDIM * 2 * CDIM];
__device__ __half g_Wp16 [CDIM * CDIM];
__device__ __half g_R16  [RROWS * CDIM];       // region fp16
__device__ __half g_kv16 [RROWS * 2 * CDIM];   // kv output fp16
__device__ __half g_QKT  [BATCH * CDIM * HR];  // (768 x 384) per batch
__device__ __half g_VP   [BATCH * HR * CDIM];  // (384 x 768) per batch
__device__ float  g_qb   [BATCH * HR];
__device__ float  g_S    [MROWS * HR];         // raw scores fp32
__device__ __half g_attn [MROWS * HR];         // softmaxed fp16

// ---------------- fp32 -> fp16 convert -------------------------------------
__global__ void cvt_f32_f16(const float* __restrict__ in, __half* __restrict__ out, int n4)
{
    int i = blockIdx.x * blockDim.x + threadIdx.x;
    if (i < n4) {
        float4 v = reinterpret_cast<const float4*>(in)[i];
        __half2* o = reinterpret_cast<__half2*>(out) + 2 * i;
        o[0] = __floats2half2_rn(v.x, v.y);
        o[1] = __floats2half2_rn(v.z, v.w);
    }
}

// ---------------- fp32 -> fp16 transpose (768x768) -------------------------
__global__ void transpose_cvt(const float* __restrict__ in, __half* __restrict__ out)
{
    __shared__ float t[32][33];
    int bx = blockIdx.x * 32, by = blockIdx.y * 32;
    int tx = threadIdx.x, ty = threadIdx.y;   // (32, 8)
#pragma unroll
    for (int i = 0; i < 32; i += 8)
        t[ty + i][tx] = in[(by + ty + i) * CDIM + bx + tx];
    __syncthreads();
#pragma unroll
    for (int i = 0; i < 32; i += 8)
        out[(bx + ty + i) * CDIM + by + tx] = __float2half(t[tx][ty + i]);
}

// ---------------- mma helpers ----------------------------------------------
__device__ __forceinline__ void ldsm_x4(u32* r, const void* p)
{
    u32 a = (u32)__cvta_generic_to_shared(p);
    asm volatile("ldmatrix.sync.aligned.m8n8.x4.shared.b16 {%0,%1,%2,%3}, [%4];\n"
                 : "=r"(r[0]), "=r"(r[1]), "=r"(r[2]), "=r"(r[3]) : "r"(a));
}
__device__ __forceinline__ void ldsm_x2t(u32* r, const void* p)
{
    u32 a = (u32)__cvta_generic_to_shared(p);
    asm volatile("ldmatrix.sync.aligned.m8n8.x2.trans.shared.b16 {%0,%1}, [%2];\n"
                 : "=r"(r[0]), "=r"(r[1]) : "r"(a));
}
__device__ __forceinline__ void mma_16816(float* c, const u32* a, const u32* b)
{
    asm volatile("mma.sync.aligned.m16n8k16.row.col.f32.f16.f16.f32 "
                 "{%0,%1,%2,%3}, {%4,%5,%6,%7}, {%8,%9}, {%0,%1,%2,%3};\n"
                 : "+f"(c[0]), "+f"(c[1]), "+f"(c[2]), "+f"(c[3])
                 : "r"(a[0]), "r"(a[1]), "r"(a[2]), "r"(a[3]), "r"(b[0]), "r"(b[1]));
}

__device__ __forceinline__ void store2(__half* p, float x, float y)
{
    *reinterpret_cast<__half2*>(p) = __floats2half2_rn(x, y);
}
__device__ __forceinline__ void store2(float* p, float x, float y)
{
    float2 v; v.x = x; v.y = y;
    *reinterpret_cast<float2*>(p) = v;
}

// ---------------- batched fp16 GEMM: C[b] = A[b] @ W[b] + bias[b] ----------
// BM=128 BN=128 BK=32, 256 threads (8 warps as 4m x 2n, warp tile 32x64)
template <typename OutT>
__global__ void __launch_bounds__(256)
hgemm(const __half* __restrict__ A0, const __half* __restrict__ W0,
      const float* __restrict__ bias0, OutT* __restrict__ C0,
      int M, int N, int K, int sA, int sW, int sBias, int sC)
{
    const int BK = 32;
    __shared__ __half As[128][BK + 8];
    __shared__ __half Bs[BK][128 + 8];

    const int bz = blockIdx.z;
    const __half* A = A0 + (long)bz * sA;
    const __half* W = W0 + (long)bz * sW;
    const float* bias = bias0 + (long)bz * sBias;
    OutT* C = C0 + (long)bz * sC;

    const int tid  = threadIdx.x;
    const int warp = tid >> 5;
    const int lane = tid & 31;
    const int bm = blockIdx.y * 128;
    const int bn = blockIdx.x * 128;
    const int wm = (warp & 3) * 32;   // warp row offset
    const int wn = (warp >> 2) * 64;  // warp col offset

    float acc[2][8][4];
#pragma unroll
    for (int mi = 0; mi < 2; mi++)
#pragma unroll
        for (int ni = 0; ni < 8; ni++)
#pragma unroll
            for (int j = 0; j < 4; j++) acc[mi][ni][j] = 0.f;

    int a_row[2], a_col[2], b_row[2], b_col[2];
#pragma unroll
    for (int i = 0; i < 2; i++) {
        int idx = tid + i * 256;
        a_row[i] = idx >> 2;  a_col[i] = (idx & 3) * 8;   // 128 rows x 4 chunks
        b_row[i] = idx >> 4;  b_col[i] = (idx & 15) * 8;  // 32 rows x 16 chunks
    }

    uint4 pa[2], pb[2];
#pragma unroll
    for (int i = 0; i < 2; i++) {
        pa[i] = *reinterpret_cast<const uint4*>(A + (bm + a_row[i]) * K + a_col[i]);
        pb[i] = *reinterpret_cast<const uint4*>(W + b_row[i] * N + bn + b_col[i]);
    }

    const int nk = K / BK;
    for (int kt = 0; kt < nk; kt++) {
#pragma unroll
        for (int i = 0; i < 2; i++) {
            *reinterpret_cast<uint4*>(&As[a_row[i]][a_col[i]]) = pa[i];
            *reinterpret_cast<uint4*>(&Bs[b_row[i]][b_col[i]]) = pb[i];
        }
        __syncthreads();

        if (kt + 1 < nk) {
            int k0 = (kt + 1) * BK;
#pragma unroll
            for (int i = 0; i < 2; i++) {
                pa[i] = *reinterpret_cast<const uint4*>(A + (bm + a_row[i]) * K + k0 + a_col[i]);
                pb[i] = *reinterpret_cast<const uint4*>(W + (k0 + b_row[i]) * N + bn + b_col[i]);
            }
        }

#pragma unroll
        for (int kk = 0; kk < 2; kk++) {
            u32 af[2][4], bf[8][2];
#pragma unroll
            for (int mi = 0; mi < 2; mi++)
                ldsm_x4(af[mi], &As[wm + mi * 16 + (lane & 15)][kk * 16 + (lane >> 4) * 8]);
#pragma unroll
            for (int ni = 0; ni < 8; ni++)
                ldsm_x2t(bf[ni], &Bs[kk * 16 + (lane & 15)][wn + ni * 8]);
#pragma unroll
            for (int mi = 0; mi < 2; mi++)
#pragma unroll
                for (int ni = 0; ni < 8; ni++)
                    mma_16816(acc[mi][ni], af[mi], bf[ni]);
        }
        __syncthreads();
    }

    const int g  = lane >> 2;
    const int t2 = (lane & 3) * 2;
#pragma unroll
    for (int mi = 0; mi < 2; mi++) {
#pragma unroll
        for (int ni = 0; ni < 8; ni++) {
            int row = bm + wm + mi * 16 + g;
            int col = bn + wn + ni * 8 + t2;
            float b0 = bias[col], b1 = bias[col + 1];
            store2(C + row * N + col,       acc[mi][ni][0] + b0, acc[mi][ni][1] + b1);
            store2(C + (row + 8) * N + col, acc[mi][ni][2] + b0, acc[mi][ni][3] + b1);
        }
    }
}

// ---------------- kv -> QKT, VP projections --------------------------------
// grid (B*H, CDIM/128), block 128. Thread = one output column c.
__global__ void __launch_bounds__(128)
project_kv(const __half* __restrict__ kv, const __half* __restrict__ WqT,
           const __half* __restrict__ Wp, __half* __restrict__ QKT,
           __half* __restrict__ VP)
{
    const int bh = blockIdx.x;
    const int b = bh / NHEAD, h = bh % NHEAD;
    const int c = blockIdx.y * 128 + threadIdx.x;

    __shared__ float ksm[NR][HDIM];
    __shared__ float vsm[NR][HDIM];

    // load k,v tiles for (b,h): 2048 halves each
    for (int i = threadIdx.x; i < NR * HDIM / 8; i += 128) {
        int r = (i * 8) / HDIM;
        int d = (i * 8) % HDIM;
        const __half* src = kv + (b * NR + r) * (2 * CDIM) + h * HDIM + d;
        uint4 kraw = *reinterpret_cast<const uint4*>(src);
        uint4 vraw = *reinterpret_cast<const uint4*>(src + CDIM);
        const __half2* kh = reinterpret_cast<const __half2*>(&kraw);
        const __half2* vh = reinterpret_cast<const __half2*>(&vraw);
#pragma unroll
        for (int j = 0; j < 4; j++) {
            float2 fk = __half22float2(kh[j]);
            float2 fv = __half22float2(vh[j]);
            ksm[r][d + 2 * j]     = fk.x;
            ksm[r][d + 2 * j + 1] = fk.y;
            vsm[r][d + 2 * j]     = fv.x;
            vsm[r][d + 2 * j + 1] = fv.y;
        }
    }
    __syncthreads();

    float acc[NR];

    // QKT[b][c][h*32+r] = sum_d WqT[hD+d, c] * k[r][d]
#pragma unroll
    for (int r = 0; r < NR; r++) acc[r] = 0.f;
    for (int d = 0; d < HDIM; d++) {
        float w = __half2float(WqT[(h * HDIM + d) * CDIM + c]);
#pragma unroll
        for (int r = 0; r < NR; r++) acc[r] += ksm[r][d] * w;
    }
    {
        __half* dst = QKT + (long)b * CDIM * HR + c * HR + h * NR;
#pragma unroll
        for (int r = 0; r < NR; r++) dst[r] = __float2half(acc[r]);
    }

    // VP[b][h*32+r][c] = sum_d v[r][d] * Wp[hD+d, c]
#pragma unroll
    for (int r = 0; r < NR; r++) acc[r] = 0.f;
    for (int d = 0; d < HDIM; d++) {
        float w = __half2float(Wp[(h * HDIM + d) * CDIM + c]);
#pragma unroll
        for (int r = 0; r < NR; r++) acc[r] += vsm[r][d] * w;
    }
    {
        __half* dst = VP + (long)b * HR * CDIM + h * NR * CDIM + c;
#pragma unroll
        for (int r = 0; r < NR; r++) dst[r * CDIM] = __float2half(acc[r]);
    }
}

// ---------------- qb[b][hr] = bq_h . k[b,r,h,:] ----------------------------
__global__ void qb_kernel(const __half* __restrict__ kv, const float* __restrict__ bq,
                          float* __restrict__ qb)
{
    int b = blockIdx.x;
    int hr = threadIdx.x;             // 384
    int h = hr / NR, r = hr % NR;
    const __half* kk = kv + (b * NR + r) * (2 * CDIM) + h * HDIM;
    float a = 0.f;
#pragma unroll
    for (int d = 0; d < HDIM; d++) a += bq[h * HDIM + d] * __half2float(kk[d]);
    qb[b * HR + hr] = a;
}

// ---------------- softmax: attn = softmax(S*scale*p2r + 1e-8) --------------
// thread = one (row, h); reads 32 fp32 scores + 32 p2r, writes 32 fp16
__global__ void __launch_bounds__(256)
softmax_kernel(const float* __restrict__ S, const float* __restrict__ P2R,
               __half* __restrict__ attn)
{
    int gidx = blockIdx.x * 256 + threadIdx.x;    // over MROWS*NHEAD
    int row = gidx / NHEAD;
    int h = gidx % NHEAD;

    const float4* sp = reinterpret_cast<const float4*>(S + (long)row * HR + h * NR);
    const float4* wp = reinterpret_cast<const float4*>(P2R + (long)row * NR);

    float s[NR];
#pragma unroll
    for (int j = 0; j < NR / 4; j++) {
        float4 sv = sp[j];
        float4 w  = wp[j];
        s[4 * j + 0] = sv.x * (0.125f * w.x) + 1e-8f;
        s[4 * j + 1] = sv.y * (0.125f * w.y) + 1e-8f;
        s[4 * j + 2] = sv.z * (0.125f * w.z) + 1e-8f;
        s[4 * j + 3] = sv.w * (0.125f * w.w) + 1e-8f;
    }

    float m = s[0];
#pragma unroll
    for (int r = 1; r < NR; r++) m = fmaxf(m, s[r]);
    float sum = 0.f;
#pragma unroll
    for (int r = 0; r < NR; r++) { s[r] = __expf(s[r] - m); sum += s[r]; }
    float inv = 1.0f / sum;

    __half2 packed[NR / 2];
#pragma unroll
    for (int j = 0; j < NR / 2; j++)
        packed[j] = __floats2half2_rn(s[2 * j] * inv, s[2 * j + 1] * inv);

    uint4* dst = reinterpret_cast<uint4*>(attn + (long)row * HR + h * NR);
    const uint4* src = reinterpret_cast<const uint4*>(packed);
#pragma unroll
    for (int j = 0; j < 4; j++) dst[j] = src[j];
}

// ---------------- launcher -------------------------------------------------
extern "C" void kernel_launch(void* const* d_in, const int* in_sizes, int n_in,
                              void* d_out, int out_size)
{
    const float* patch  = (const float*)d_in[0];
    const float* region = (const float*)d_in[1];
    const float* p2r    = (const float*)d_in[2];
    const float* Wq     = (const float*)d_in[3];
    const float* bq     = (const float*)d_in[4];
    const float* Wkv    = (const float*)d_in[5];
    const float* bkv    = (const float*)d_in[6];
    const float* Wp     = (const float*)d_in[7];
    const float* bp     = (const float*)d_in[8];
    float* out = (float*)d_out;

    __half *A16, *WqT16, *Wkv16, *Wp16, *R16, *kv16, *QKT, *VP, *attn;
    float *qb, *S;
    cudaGetSymbolAddress((void**)&A16,   g_A16);
    cudaGetSymbolAddress((void**)&WqT16, g_WqT16);
    cudaGetSymbolAddress((void**)&Wkv16, g_Wkv16);
    cudaGetSymbolAddress((void**)&Wp16,  g_Wp16);
    cudaGetSymbolAddress((void**)&R16,   g_R16);
    cudaGetSymbolAddress((void**)&kv16,  g_kv16);
    cudaGetSymbolAddress((void**)&QKT,   g_QKT);
    cudaGetSymbolAddress((void**)&VP,    g_VP);
    cudaGetSymbolAddress((void**)&attn,  g_attn);
    cudaGetSymbolAddress((void**)&qb,    g_qb);
    cudaGetSymbolAddress((void**)&S,     g_S);

    // fp32 -> fp16 converts (+ Wq transpose)
    {
        int n4;
        n4 = (MROWS * CDIM) / 4;      cvt_f32_f16<<<(n4 + 255) / 256, 256>>>(patch,  A16,   n4);
        n4 = (CDIM * 2 * CDIM) / 4;   cvt_f32_f16<<<(n4 + 255) / 256, 256>>>(Wkv,    Wkv16, n4);
        n4 = (CDIM * CDIM) / 4;       cvt_f32_f16<<<(n4 + 255) / 256, 256>>>(Wp,     Wp16,  n4);
        n4 = (RROWS * CDIM) / 4;      cvt_f32_f16<<<(n4 + 255) / 256, 256>>>(region, R16,   n4);
        transpose_cvt<<<dim3(CDIM / 32, CDIM / 32), dim3(32, 8)>>>(Wq, WqT16);
    }

    // kv = region @ Wkv + bkv   (256 x 1536)
    hgemm<__half><<<dim3(2 * CDIM / 128, RROWS / 128, 1), 256>>>(
        R16, Wkv16, bkv, kv16, RROWS, 2 * CDIM, CDIM, 0, 0, 0, 0);

    // QKT / VP projections + qb
    project_kv<<<dim3(BATCH * NHEAD, CDIM / 128), 128>>>(kv16, WqT16, Wp16, QKT, VP);
    qb_kernel<<<BATCH, HR>>>(kv16, bq, qb);

    // S = patch @ QKT[b] + qb[b]   batched: M=4096 N=384 K=768
    hgemm<float><<<dim3(HR / 128, NP / 128, BATCH), 256>>>(
        A16, QKT, qb, S, NP, HR, CDIM,
        NP * CDIM, CDIM * HR, HR, NP * HR);

    // attn = softmax(S * scale * p2r + 1e-8)
    softmax_kernel<<<(MROWS * NHEAD) / 256, 256>>>(S, p2r, attn);

    // out = attn @ VP[b] + bp   batched: M=4096 N=768 K=384
    hgemm<float><<<dim3(CDIM / 128, NP / 128, BATCH), 256>>>(
        attn, VP, bp, out, NP, CDIM, HR,
        NP * HR, HR * CDIM, 0, NP * CDIM);
}